// round 1
// baseline (speedup 1.0000x reference)
#include <cuda_runtime.h>
#include <cuda_bf16.h>
#include <math.h>

// ---------------------------------------------------------------------------
// MolecularGNN: 3x GCNConv(+BN+ReLU) -> global mean pool -> MLP head
// N=100000 nodes, E=3200000 edges, G=4096 graphs
// dims: 36 -> 128 -> 128 -> 64 ; head 64->128->64->2
// ---------------------------------------------------------------------------

#define N_NODES  100000
#define N_EDGES  3200000
#define N_GRAPHS 4096
#define BN_EPS   1e-5f

// ---- scratch (device globals; allocation-free rule) -----------------------
__device__ __align__(256) float g_deg [N_NODES];
__device__ __align__(256) float g_dinv[N_NODES];
__device__ __align__(256) float g_bufA[N_NODES * 128]; // xw scratch
__device__ __align__(256) float g_bufB[N_NODES * 128]; // agg/h ping
__device__ __align__(256) float g_bufC[N_NODES * 128]; // agg/h pong
__device__ __align__(256) float g_sums[N_GRAPHS * 64];
__device__ __align__(256) float g_cnt [N_GRAPHS];

// ---- helpers --------------------------------------------------------------
__device__ __forceinline__ void red_add_f32(float* p, float v) {
    asm volatile("red.global.add.f32 [%0], %1;" :: "l"(p), "f"(v) : "memory");
}
__device__ __forceinline__ void red_add_v4(float* p, float4 m) {
    asm volatile("red.global.add.v4.f32 [%0], {%1,%2,%3,%4};"
                 :: "l"(p), "f"(m.x), "f"(m.y), "f"(m.z), "f"(m.w) : "memory");
}

// ---- degree / normalization ----------------------------------------------
__global__ void deg_init_kernel() {
    int i = blockIdx.x * blockDim.x + threadIdx.x;
    if (i < N_NODES) g_deg[i] = 1.0f; // self loop
}

__global__ void deg_count_kernel(const int* __restrict__ dst) {
    int stride = gridDim.x * blockDim.x;
    for (int e = blockIdx.x * blockDim.x + threadIdx.x; e < N_EDGES; e += stride)
        red_add_f32(&g_deg[dst[e]], 1.0f);
}

__global__ void dinv_kernel() {
    int i = blockIdx.x * blockDim.x + threadIdx.x;
    if (i < N_NODES) g_dinv[i] = rsqrtf(g_deg[i]);
}

// ---- GEMM: xw = h @ W ; agg_init = xw * dinv^2 + b ------------------------
// blockDim = FOUT, each block does ROWS=16 rows, K chunked into smem.
template<int FIN, int FOUT, int KCHUNK>
__global__ void gemm_kernel(const float* __restrict__ in,
                            const float* __restrict__ W,
                            const float* __restrict__ bias,
                            float* __restrict__ xw,
                            float* __restrict__ agg)
{
    constexpr int ROWS = 16;
    __shared__ float Ws[KCHUNK][FOUT];
    __shared__ float hs[ROWS][KCHUNK];

    const int row0 = blockIdx.x * ROWS;
    const int tid  = threadIdx.x;

    float acc[ROWS];
#pragma unroll
    for (int r = 0; r < ROWS; r++) acc[r] = 0.0f;

    for (int kc = 0; kc < FIN; kc += KCHUNK) {
        // load W chunk (each thread owns column tid)
#pragma unroll
        for (int i = tid; i < KCHUNK * FOUT; i += FOUT)
            Ws[i / FOUT][tid] = W[(kc + i / FOUT) * FOUT + tid];
        // load 16 rows of h, KCHUNK wide, vectorized
        constexpr int HV = ROWS * KCHUNK / 4;
        for (int i = tid; i < HV; i += FOUT) {
            int r  = i / (KCHUNK / 4);
            int c4 = i % (KCHUNK / 4);
            float4 v = *reinterpret_cast<const float4*>(
                &in[(size_t)(row0 + r) * FIN + kc + c4 * 4]);
            *reinterpret_cast<float4*>(&hs[r][c4 * 4]) = v;
        }
        __syncthreads();

#pragma unroll
        for (int k = 0; k < KCHUNK; k += 4) {
            float w0 = Ws[k + 0][tid];
            float w1 = Ws[k + 1][tid];
            float w2 = Ws[k + 2][tid];
            float w3 = Ws[k + 3][tid];
#pragma unroll
            for (int r = 0; r < ROWS; r++) {
                float4 h4 = *reinterpret_cast<const float4*>(&hs[r][k]);
                float a = acc[r];
                a = fmaf(h4.x, w0, a);
                a = fmaf(h4.y, w1, a);
                a = fmaf(h4.z, w2, a);
                a = fmaf(h4.w, w3, a);
                acc[r] = a;
            }
        }
        __syncthreads();
    }

    const float bv = bias[tid];
#pragma unroll
    for (int r = 0; r < ROWS; r++) {
        int row = row0 + r;
        float di = g_dinv[row];
        float ns = di * di;            // self-loop coeff 1/deg
        size_t o = (size_t)row * FOUT + tid;
        xw[o]  = acc[r];
        agg[o] = fmaf(acc[r], ns, bv);
    }
}

// ---- edge aggregation: agg[dst] += xw[src] * dinv[src]*dinv[dst] ----------
// One warp-segment of CH lanes (CH = FOUT/4 float4 chunks) per edge.
template<int FOUT>
__global__ void agg_kernel(const int* __restrict__ src,
                           const int* __restrict__ dst,
                           const float* __restrict__ xw,
                           float* __restrict__ agg)
{
    constexpr int CH  = FOUT / 4;  // 32 or 16
    constexpr int EPW = 32 / CH;   // edges per warp
    const int lane   = threadIdx.x & 31;
    const int warp   = (blockIdx.x * blockDim.x + threadIdx.x) >> 5;
    const int nWarps = (gridDim.x * blockDim.x) >> 5;
    const int seg    = lane / CH;
    const int c      = lane % CH;
    const int root   = seg * CH;

    for (long base = (long)warp * EPW; base < N_EDGES; base += (long)nWarps * EPW) {
        long e = base + seg;
        int s = 0, d = 0;
        float wgt = 0.0f;
        bool valid = (e < N_EDGES);
        if (c == 0 && valid) {
            s = src[e];
            d = dst[e];
            wgt = g_dinv[s] * g_dinv[d];
        }
        s   = __shfl_sync(0xffffffffu, s,   root);
        d   = __shfl_sync(0xffffffffu, d,   root);
        wgt = __shfl_sync(0xffffffffu, wgt, root);
        if (!valid) continue;

        float4 v = reinterpret_cast<const float4*>(xw)[(size_t)s * CH + c];
        v.x *= wgt; v.y *= wgt; v.z *= wgt; v.w *= wgt;
        red_add_v4(agg + (size_t)d * FOUT + c * 4, v);
    }
}

// ---- BN (eval) + ReLU in place -------------------------------------------
template<int FOUT>
__global__ void bnrelu_kernel(float* __restrict__ a,
                              const float* __restrict__ g,
                              const float* __restrict__ be,
                              const float* __restrict__ m,
                              const float* __restrict__ v)
{
    __shared__ float sc[FOUT], sh[FOUT];
    for (int i = threadIdx.x; i < FOUT; i += blockDim.x) {
        float s = g[i] * rsqrtf(v[i] + BN_EPS);
        sc[i] = s;
        sh[i] = be[i] - m[i] * s;
    }
    __syncthreads();

    const int n4 = N_NODES * FOUT / 4;
    int stride = gridDim.x * blockDim.x;
    float4* p = reinterpret_cast<float4*>(a);
    for (int i = blockIdx.x * blockDim.x + threadIdx.x; i < n4; i += stride) {
        int col = (i * 4) % FOUT;
        float4 x = p[i];
        x.x = fmaxf(fmaf(x.x, sc[col + 0], sh[col + 0]), 0.0f);
        x.y = fmaxf(fmaf(x.y, sc[col + 1], sh[col + 1]), 0.0f);
        x.z = fmaxf(fmaf(x.z, sc[col + 2], sh[col + 2]), 0.0f);
        x.w = fmaxf(fmaf(x.w, sc[col + 3], sh[col + 3]), 0.0f);
        p[i] = x;
    }
}

// ---- pooling --------------------------------------------------------------
__global__ void pool_zero_kernel() {
    int i = blockIdx.x * blockDim.x + threadIdx.x;
    if (i < N_GRAPHS * 64) g_sums[i] = 0.0f;
    if (i < N_GRAPHS)      g_cnt[i]  = 0.0f;
}

__global__ void pool_kernel(const float* __restrict__ h,
                            const int* __restrict__ batch)
{
    const int total = N_NODES * 16;  // float4 chunks of 64-wide rows
    int stride = gridDim.x * blockDim.x;
    for (int i = blockIdx.x * blockDim.x + threadIdx.x; i < total; i += stride) {
        int n = i >> 4;
        int c = i & 15;
        int g = batch[n];
        float4 v = reinterpret_cast<const float4*>(h)[i];
        red_add_v4(&g_sums[(size_t)g * 64 + c * 4], v);
        if (c == 0) red_add_f32(&g_cnt[g], 1.0f);
    }
}

// ---- MLP head: one block (128 thr) per graph ------------------------------
__global__ void head_kernel(const float* __restrict__ fw0, const float* __restrict__ fb0,
                            const float* __restrict__ fw1, const float* __restrict__ fb1,
                            const float* __restrict__ ow,  const float* __restrict__ ob,
                            float* __restrict__ out)
{
    __shared__ float pooled[64], h0[128], h1[64];
    const int g = blockIdx.x;
    const int t = threadIdx.x;

    float inv = 1.0f / fmaxf(g_cnt[g], 1.0f);
    if (t < 64) pooled[t] = g_sums[(size_t)g * 64 + t] * inv;
    __syncthreads();

    float a = fb0[t];
#pragma unroll
    for (int k = 0; k < 64; k++) a = fmaf(pooled[k], fw0[k * 128 + t], a);
    h0[t] = fmaxf(a, 0.0f);
    __syncthreads();

    if (t < 64) {
        float b = fb1[t];
#pragma unroll
        for (int k = 0; k < 128; k++) b = fmaf(h0[k], fw1[k * 64 + t], b);
        h1[t] = fmaxf(b, 0.0f);
    }
    __syncthreads();

    if (t < 2) {
        float o = ob[t];
#pragma unroll
        for (int k = 0; k < 64; k++) o = fmaf(h1[k], ow[k * 2 + t], o);
        out[(size_t)g * 2 + t] = o;
    }
}

// ---------------------------------------------------------------------------
extern "C" void kernel_launch(void* const* d_in, const int* in_sizes, int n_in,
                              void* d_out, int out_size)
{
    const float* x          = (const float*)d_in[0];
    const int*   edge_index = (const int*)  d_in[1];
    const int*   batch      = (const int*)  d_in[2];

    // num_graphs may or may not be materialized as an input; detect by size.
    int p = 3;
    if (in_sizes[3] == 1) p = 4;

    const float* W [3];
    const float* B [3];
    const float* Gm[3];
    const float* Be[3];
    const float* Mn[3];
    const float* Vr[3];
    for (int l = 0; l < 3; l++) {
        W [l] = (const float*)d_in[p + 6 * l + 0];
        B [l] = (const float*)d_in[p + 6 * l + 1];
        Gm[l] = (const float*)d_in[p + 6 * l + 2];
        Be[l] = (const float*)d_in[p + 6 * l + 3];
        Mn[l] = (const float*)d_in[p + 6 * l + 4];
        Vr[l] = (const float*)d_in[p + 6 * l + 5];
    }
    const float* fw0 = (const float*)d_in[p + 18];
    const float* fb0 = (const float*)d_in[p + 19];
    const float* fw1 = (const float*)d_in[p + 20];
    const float* fb1 = (const float*)d_in[p + 21];
    const float* ow  = (const float*)d_in[p + 22];
    const float* ob  = (const float*)d_in[p + 23];
    float* out = (float*)d_out;

    const int* src = edge_index;
    const int* dst = edge_index + N_EDGES;

    float *bufA, *bufB, *bufC;
    cudaGetSymbolAddress((void**)&bufA, g_bufA);
    cudaGetSymbolAddress((void**)&bufB, g_bufB);
    cudaGetSymbolAddress((void**)&bufC, g_bufC);

    // normalization
    deg_init_kernel<<<(N_NODES + 255) / 256, 256>>>();
    deg_count_kernel<<<2048, 256>>>(dst);
    dinv_kernel<<<(N_NODES + 255) / 256, 256>>>();

    const int GEMM_BLOCKS = N_NODES / 16;   // 6250 (exact)
    const int AGG_BLOCKS  = 2048;
    const int EW_BLOCKS   = 2048;

    // ---- layer 0: x[36] -> B[128]
    gemm_kernel<36, 128, 36><<<GEMM_BLOCKS, 128>>>(x, W[0], B[0], bufA, bufB);
    agg_kernel<128><<<AGG_BLOCKS, 256>>>(src, dst, bufA, bufB);
    bnrelu_kernel<128><<<EW_BLOCKS, 256>>>(bufB, Gm[0], Be[0], Mn[0], Vr[0]);

    // ---- layer 1: B[128] -> C[128]
    gemm_kernel<128, 128, 64><<<GEMM_BLOCKS, 128>>>(bufB, W[1], B[1], bufA, bufC);
    agg_kernel<128><<<AGG_BLOCKS, 256>>>(src, dst, bufA, bufC);
    bnrelu_kernel<128><<<EW_BLOCKS, 256>>>(bufC, Gm[1], Be[1], Mn[1], Vr[1]);

    // ---- layer 2: C[128] -> B[64]
    gemm_kernel<128, 64, 64><<<GEMM_BLOCKS, 64>>>(bufC, W[2], B[2], bufA, bufB);
    agg_kernel<64><<<AGG_BLOCKS, 256>>>(src, dst, bufA, bufB);
    bnrelu_kernel<64><<<EW_BLOCKS, 256>>>(bufB, Gm[2], Be[2], Mn[2], Vr[2]);

    // ---- pool + head
    pool_zero_kernel<<<(N_GRAPHS * 64 + 255) / 256, 256>>>();
    pool_kernel<<<2048, 256>>>(bufB, batch);
    head_kernel<<<N_GRAPHS, 128>>>(fw0, fb0, fw1, fb1, ow, ob, out);
}

// round 3
// speedup vs baseline: 1.7211x; 1.7211x over previous
#include <cuda_runtime.h>
#include <cuda_bf16.h>
#include <math.h>

// ---------------------------------------------------------------------------
// MolecularGNN: 3x GCNConv(+BN+ReLU) -> global mean pool -> MLP head
// CSR-gather formulation: no float scatter atomics in the hot path.
// (Round-2 resubmit: Round-2 bench failed with a harness-init device-busy
//  error before any kernel ran — infra flake, not a kernel defect.)
// ---------------------------------------------------------------------------

#define N_NODES  100000
#define N_EDGES  3200000
#define N_GRAPHS 4096
#define BN_EPS   1e-5f

// ---- scratch (device globals; allocation-free rule) -----------------------
__device__ __align__(256) int   g_ecnt  [N_NODES];
__device__ __align__(256) int   g_off   [N_NODES + 1];
__device__ __align__(256) int   g_cursor[N_NODES];
__device__ __align__(256) float g_dinv  [N_NODES];
__device__ __align__(256) int2  g_csr   [N_EDGES];        // (src, f32 weight bits)
__device__ __align__(256) float g_bufA  [N_NODES * 128];  // xw
__device__ __align__(256) float g_bufB  [N_NODES * 128];  // h
__device__ __align__(256) float g_sums  [N_GRAPHS * 64];
__device__ __align__(256) float g_cnt   [N_GRAPHS];

__device__ __forceinline__ void red_add_f32(float* p, float v) {
    asm volatile("red.global.add.f32 [%0], %1;" :: "l"(p), "f"(v) : "memory");
}

// ---- degree count ---------------------------------------------------------
__global__ void deg_zero_kernel() {
    int i = blockIdx.x * blockDim.x + threadIdx.x;
    if (i < N_NODES) g_ecnt[i] = 0;
}

__global__ void deg_count_kernel(const int* __restrict__ dst) {
    int stride = gridDim.x * blockDim.x;
    for (int e = blockIdx.x * blockDim.x + threadIdx.x; e < N_EDGES; e += stride)
        atomicAdd(&g_ecnt[dst[e]], 1);
}

// ---- exclusive prefix sum over g_ecnt (single block, warp-scan) -----------
__global__ void scan_kernel() {
    __shared__ int warpsum[32];
    __shared__ int warpoff[32];
    const int tid  = threadIdx.x;
    const int lane = tid & 31;
    const int wid  = tid >> 5;
    int running = 0;
    for (int base = 0; base < N_NODES; base += 1024) {
        int i = base + tid;
        int v = (i < N_NODES) ? g_ecnt[i] : 0;
        int s = v;
#pragma unroll
        for (int o = 1; o < 32; o <<= 1) {
            int t = __shfl_up_sync(0xffffffffu, s, o);
            if (lane >= o) s += t;
        }
        if (lane == 31) warpsum[wid] = s;
        __syncthreads();
        if (wid == 0) {
            int ws = warpsum[lane];
            int t  = ws;
#pragma unroll
            for (int o = 1; o < 32; o <<= 1) {
                int u = __shfl_up_sync(0xffffffffu, t, o);
                if (lane >= o) t += u;
            }
            warpoff[lane] = t - ws;          // exclusive
            if (lane == 31) warpsum[0] = t;  // chunk total
        }
        __syncthreads();
        int incl = s + warpoff[wid];
        if (i < N_NODES) g_off[i] = running + incl - v;
        int total = warpsum[0];
        __syncthreads();
        running += total;
    }
    if (tid == 0) g_off[N_NODES] = running;
}

// ---- dinv + cursor init ---------------------------------------------------
__global__ void dinv_kernel() {
    int i = blockIdx.x * blockDim.x + threadIdx.x;
    if (i < N_NODES) {
        g_dinv[i]   = rsqrtf((float)g_ecnt[i] + 1.0f);
        g_cursor[i] = g_off[i];
    }
}

// ---- CSR fill -------------------------------------------------------------
__global__ void fill_kernel(const int* __restrict__ src, const int* __restrict__ dst) {
    int stride = gridDim.x * blockDim.x;
    for (int e = blockIdx.x * blockDim.x + threadIdx.x; e < N_EDGES; e += stride) {
        int s = src[e];
        int d = dst[e];
        int pos = atomicAdd(&g_cursor[d], 1);
        float w = g_dinv[s] * g_dinv[d];
        g_csr[pos] = make_int2(s, __float_as_int(w));
    }
}

// ---- GEMM: xw = in @ W ----------------------------------------------------
template<int FIN, int FOUT, int KCHUNK>
__global__ void gemm_kernel(const float* __restrict__ in,
                            const float* __restrict__ W,
                            float* __restrict__ xw)
{
    constexpr int ROWS = 16;
    __shared__ float Ws[KCHUNK][FOUT];
    __shared__ float hs[ROWS][KCHUNK];

    const int row0 = blockIdx.x * ROWS;
    const int tid  = threadIdx.x;

    float acc[ROWS];
#pragma unroll
    for (int r = 0; r < ROWS; r++) acc[r] = 0.0f;

    for (int kc = 0; kc < FIN; kc += KCHUNK) {
#pragma unroll
        for (int i = tid; i < KCHUNK * FOUT; i += FOUT)
            Ws[i / FOUT][tid] = W[(kc + i / FOUT) * FOUT + tid];
        constexpr int HV = ROWS * KCHUNK / 4;
        for (int i = tid; i < HV; i += FOUT) {
            int r  = i / (KCHUNK / 4);
            int c4 = i % (KCHUNK / 4);
            float4 v = *reinterpret_cast<const float4*>(
                &in[(size_t)(row0 + r) * FIN + kc + c4 * 4]);
            *reinterpret_cast<float4*>(&hs[r][c4 * 4]) = v;
        }
        __syncthreads();

#pragma unroll
        for (int k = 0; k < KCHUNK; k += 4) {
            float w0 = Ws[k + 0][tid];
            float w1 = Ws[k + 1][tid];
            float w2 = Ws[k + 2][tid];
            float w3 = Ws[k + 3][tid];
#pragma unroll
            for (int r = 0; r < ROWS; r++) {
                float4 h4 = *reinterpret_cast<const float4*>(&hs[r][k]);
                float a = acc[r];
                a = fmaf(h4.x, w0, a);
                a = fmaf(h4.y, w1, a);
                a = fmaf(h4.z, w2, a);
                a = fmaf(h4.w, w3, a);
                acc[r] = a;
            }
        }
        __syncthreads();
    }

#pragma unroll
    for (int r = 0; r < ROWS; r++)
        xw[(size_t)(row0 + r) * FOUT + tid] = acc[r];
}

// ---- fused CSR aggregation + self-loop + bias + BN + ReLU (+ pool) --------
// One warp per dst node; 8 nodes per 256-thread block.
template<int FOUT, bool POOL>
__global__ void agg_kernel(const float* __restrict__ xw,
                           const float* __restrict__ bias,
                           const float* __restrict__ bn_g,
                           const float* __restrict__ bn_b,
                           const float* __restrict__ bn_m,
                           const float* __restrict__ bn_v,
                           float* __restrict__ out,
                           const int* __restrict__ batch)
{
    constexpr int VEC = FOUT / 32;        // 4 (FOUT=128) or 2 (FOUT=64)
    __shared__ float s_sc [FOUT];
    __shared__ float s_shb[FOUT];

    const int tid  = threadIdx.x;
    const int lane = tid & 31;
    const int wid  = tid >> 5;

    if (tid < FOUT) {
        float sc = bn_g[tid] * rsqrtf(bn_v[tid] + BN_EPS);
        s_sc [tid] = sc;
        s_shb[tid] = sc * (bias[tid] - bn_m[tid]) + bn_b[tid];
    }
    __syncthreads();

    const int node = blockIdx.x * 8 + wid;
    if (node >= N_NODES) return;

    const int beg = g_off[node];
    const int end = g_off[node + 1];

    float acc[VEC];
#pragma unroll
    for (int k = 0; k < VEC; k++) acc[k] = 0.0f;

    int b = beg;
    const int nfull = (end - beg) & ~31;
    for (; b < beg + nfull; b += 32) {
        int2 pk = g_csr[b + lane];
#pragma unroll 8
        for (int j = 0; j < 32; j++) {
            int   s   = __shfl_sync(0xffffffffu, pk.x, j);
            float wgt = __int_as_float(__shfl_sync(0xffffffffu, pk.y, j));
            if constexpr (VEC == 4) {
                float4 vv = reinterpret_cast<const float4*>(xw)[(size_t)s * 32 + lane];
                acc[0] = fmaf(vv.x, wgt, acc[0]);
                acc[1] = fmaf(vv.y, wgt, acc[1]);
                acc[2] = fmaf(vv.z, wgt, acc[2]);
                acc[3] = fmaf(vv.w, wgt, acc[3]);
            } else {
                float2 vv = reinterpret_cast<const float2*>(xw)[(size_t)s * 32 + lane];
                acc[0] = fmaf(vv.x, wgt, acc[0]);
                acc[1] = fmaf(vv.y, wgt, acc[1]);
            }
        }
    }
    if (b < end) {
        int e = b + lane;
        int   ssrc = 0;
        float swgt = 0.0f;
        if (e < end) {
            int2 pk = g_csr[e];
            ssrc = pk.x;
            swgt = __int_as_float(pk.y);
        }
        int cnt = end - b;
        for (int j = 0; j < cnt; j++) {
            int   s   = __shfl_sync(0xffffffffu, ssrc, j);
            float wgt = __shfl_sync(0xffffffffu, swgt, j);
            if constexpr (VEC == 4) {
                float4 vv = reinterpret_cast<const float4*>(xw)[(size_t)s * 32 + lane];
                acc[0] = fmaf(vv.x, wgt, acc[0]);
                acc[1] = fmaf(vv.y, wgt, acc[1]);
                acc[2] = fmaf(vv.z, wgt, acc[2]);
                acc[3] = fmaf(vv.w, wgt, acc[3]);
            } else {
                float2 vv = reinterpret_cast<const float2*>(xw)[(size_t)s * 32 + lane];
                acc[0] = fmaf(vv.x, wgt, acc[0]);
                acc[1] = fmaf(vv.y, wgt, acc[1]);
            }
        }
    }

    // self loop
    {
        float di = g_dinv[node];
        float ns = di * di;
        if constexpr (VEC == 4) {
            float4 sv = reinterpret_cast<const float4*>(xw)[(size_t)node * 32 + lane];
            acc[0] = fmaf(sv.x, ns, acc[0]);
            acc[1] = fmaf(sv.y, ns, acc[1]);
            acc[2] = fmaf(sv.z, ns, acc[2]);
            acc[3] = fmaf(sv.w, ns, acc[3]);
        } else {
            float2 sv = reinterpret_cast<const float2*>(xw)[(size_t)node * 32 + lane];
            acc[0] = fmaf(sv.x, ns, acc[0]);
            acc[1] = fmaf(sv.y, ns, acc[1]);
        }
    }

    // BN + ReLU
    float y[VEC];
#pragma unroll
    for (int k = 0; k < VEC; k++) {
        int col = lane * VEC + k;
        y[k] = fmaxf(fmaf(acc[k], s_sc[col], s_shb[col]), 0.0f);
    }

    if constexpr (POOL) {
        int g = batch[node];
#pragma unroll
        for (int k = 0; k < VEC; k++)
            red_add_f32(&g_sums[(size_t)g * 64 + lane * VEC + k], y[k]);
        if (lane == 0) red_add_f32(&g_cnt[g], 1.0f);
    } else {
        if constexpr (VEC == 4) {
            reinterpret_cast<float4*>(out)[(size_t)node * 32 + lane] =
                make_float4(y[0], y[1], y[2], y[3]);
        } else {
            reinterpret_cast<float2*>(out)[(size_t)node * 32 + lane] =
                make_float2(y[0], y[1]);
        }
    }
}

// ---- pooling init ---------------------------------------------------------
__global__ void pool_zero_kernel() {
    int i = blockIdx.x * blockDim.x + threadIdx.x;
    if (i < N_GRAPHS * 64) g_sums[i] = 0.0f;
    if (i < N_GRAPHS)      g_cnt[i]  = 0.0f;
}

// ---- MLP head: one block (128 thr) per graph ------------------------------
__global__ void head_kernel(const float* __restrict__ fw0, const float* __restrict__ fb0,
                            const float* __restrict__ fw1, const float* __restrict__ fb1,
                            const float* __restrict__ ow,  const float* __restrict__ ob,
                            float* __restrict__ out)
{
    __shared__ float pooled[64], h0[128], h1[64];
    const int g = blockIdx.x;
    const int t = threadIdx.x;

    float inv = 1.0f / fmaxf(g_cnt[g], 1.0f);
    if (t < 64) pooled[t] = g_sums[(size_t)g * 64 + t] * inv;
    __syncthreads();

    float a = fb0[t];
#pragma unroll
    for (int k = 0; k < 64; k++) a = fmaf(pooled[k], fw0[k * 128 + t], a);
    h0[t] = fmaxf(a, 0.0f);
    __syncthreads();

    if (t < 64) {
        float b = fb1[t];
#pragma unroll
        for (int k = 0; k < 128; k++) b = fmaf(h0[k], fw1[k * 64 + t], b);
        h1[t] = fmaxf(b, 0.0f);
    }
    __syncthreads();

    if (t < 2) {
        float o = ob[t];
#pragma unroll
        for (int k = 0; k < 64; k++) o = fmaf(h1[k], ow[k * 2 + t], o);
        out[(size_t)g * 2 + t] = o;
    }
}

// ---------------------------------------------------------------------------
extern "C" void kernel_launch(void* const* d_in, const int* in_sizes, int n_in,
                              void* d_out, int out_size)
{
    const float* x          = (const float*)d_in[0];
    const int*   edge_index = (const int*)  d_in[1];
    const int*   batch      = (const int*)  d_in[2];

    int p = 3;
    if (in_sizes[3] == 1) p = 4;   // num_graphs scalar, if materialized

    const float* W [3]; const float* B [3];
    const float* Gm[3]; const float* Be[3];
    const float* Mn[3]; const float* Vr[3];
    for (int l = 0; l < 3; l++) {
        W [l] = (const float*)d_in[p + 6 * l + 0];
        B [l] = (const float*)d_in[p + 6 * l + 1];
        Gm[l] = (const float*)d_in[p + 6 * l + 2];
        Be[l] = (const float*)d_in[p + 6 * l + 3];
        Mn[l] = (const float*)d_in[p + 6 * l + 4];
        Vr[l] = (const float*)d_in[p + 6 * l + 5];
    }
    const float* fw0 = (const float*)d_in[p + 18];
    const float* fb0 = (const float*)d_in[p + 19];
    const float* fw1 = (const float*)d_in[p + 20];
    const float* fb1 = (const float*)d_in[p + 21];
    const float* ow  = (const float*)d_in[p + 22];
    const float* ob  = (const float*)d_in[p + 23];
    float* out = (float*)d_out;

    const int* src = edge_index;
    const int* dst = edge_index + N_EDGES;

    float *bufA, *bufB;
    cudaGetSymbolAddress((void**)&bufA, g_bufA);
    cudaGetSymbolAddress((void**)&bufB, g_bufB);

    // CSR build
    deg_zero_kernel<<<(N_NODES + 255) / 256, 256>>>();
    deg_count_kernel<<<2048, 256>>>(dst);
    scan_kernel<<<1, 1024>>>();
    dinv_kernel<<<(N_NODES + 255) / 256, 256>>>();
    fill_kernel<<<2048, 256>>>(src, dst);

    const int GEMM_BLOCKS = N_NODES / 16;            // 6250 exact
    const int AGG_BLOCKS  = (N_NODES + 7) / 8;       // 12500

    // layer 0: x[36] -> A(xw) -> B(h)
    gemm_kernel<36, 128, 36><<<GEMM_BLOCKS, 128>>>(x, W[0], bufA);
    agg_kernel<128, false><<<AGG_BLOCKS, 256>>>(bufA, B[0], Gm[0], Be[0], Mn[0], Vr[0], bufB, nullptr);

    // layer 1: B -> A(xw) -> B(h)
    gemm_kernel<128, 128, 64><<<GEMM_BLOCKS, 128>>>(bufB, W[1], bufA);
    agg_kernel<128, false><<<AGG_BLOCKS, 256>>>(bufA, B[1], Gm[1], Be[1], Mn[1], Vr[1], bufB, nullptr);

    // layer 2: B -> A(xw) -> pooled sums
    gemm_kernel<128, 64, 64><<<GEMM_BLOCKS, 64>>>(bufB, W[2], bufA);
    pool_zero_kernel<<<(N_GRAPHS * 64 + 255) / 256, 256>>>();
    agg_kernel<64, true><<<AGG_BLOCKS, 256>>>(bufA, B[2], Gm[2], Be[2], Mn[2], Vr[2], nullptr, batch);

    // head
    head_kernel<<<N_GRAPHS, 128>>>(fw0, fb0, fw1, fb1, ow, ob, out);
}

// round 4
// speedup vs baseline: 2.0966x; 1.2182x over previous
#include <cuda_runtime.h>
#include <cuda_fp16.h>
#include <math.h>

// ---------------------------------------------------------------------------
// MolecularGNN: 3x GCNConv(+BN+ReLU) -> global mean pool -> MLP head
// CSR-gather + fp16 gather operand + multi-block scan.
// ---------------------------------------------------------------------------

#define N_NODES  100000
#define N_EDGES  3200000
#define N_GRAPHS 4096
#define BN_EPS   1e-5f
#define NB_SCAN  98          // ceil(100000/1024)

// ---- scratch (device globals; allocation-free rule) -----------------------
__device__ __align__(256) int    g_ecnt  [N_NODES];
__device__ __align__(256) int    g_off   [N_NODES + 1];
__device__ __align__(256) int    g_cursor[N_NODES];
__device__ __align__(256) int    g_bsum  [NB_SCAN];
__device__ __align__(256) int    g_boff  [NB_SCAN];
__device__ __align__(256) float  g_dinv  [N_NODES];
__device__ __align__(256) int2   g_csr   [N_EDGES];        // (src, f32 weight bits)
__device__ __align__(256) __half g_xw    [N_NODES * 128];  // fp16 gather operand
__device__ __align__(256) float  g_bufB  [N_NODES * 128];  // h (fp32)
__device__ __align__(256) float  g_sums  [N_GRAPHS * 64];
__device__ __align__(256) float  g_cnt   [N_GRAPHS];

__device__ __forceinline__ void red_add_f32(float* p, float v) {
    asm volatile("red.global.add.f32 [%0], %1;" :: "l"(p), "f"(v) : "memory");
}

// ---- degree count ---------------------------------------------------------
__global__ void deg_zero_kernel() {
    int i = blockIdx.x * blockDim.x + threadIdx.x;
    if (i < N_NODES) g_ecnt[i] = 0;
}

__global__ void deg_count_kernel(const int* __restrict__ dst) {
    int stride = gridDim.x * blockDim.x;
    for (int e = blockIdx.x * blockDim.x + threadIdx.x; e < N_EDGES; e += stride)
        atomicAdd(&g_ecnt[dst[e]], 1);
}

// ---- multi-block exclusive scan over g_ecnt -------------------------------
__global__ void scan_blocks_kernel() {   // NB_SCAN blocks x 1024
    __shared__ int wsum[32];
    const int t    = threadIdx.x;
    const int lane = t & 31;
    const int w    = t >> 5;
    const int i    = blockIdx.x * 1024 + t;
    int v = (i < N_NODES) ? g_ecnt[i] : 0;
    int s = v;
#pragma unroll
    for (int o = 1; o < 32; o <<= 1) {
        int u = __shfl_up_sync(0xffffffffu, s, o);
        if (lane >= o) s += u;
    }
    if (lane == 31) wsum[w] = s;
    __syncthreads();
    if (w == 0) {
        int ws = wsum[lane];
        int tt = ws;
#pragma unroll
        for (int o = 1; o < 32; o <<= 1) {
            int u = __shfl_up_sync(0xffffffffu, tt, o);
            if (lane >= o) tt += u;
        }
        wsum[lane] = tt - ws;   // exclusive warp offset
    }
    __syncthreads();
    int excl = s - v + wsum[w];
    if (i < N_NODES) g_off[i] = excl;
    if (t == 1023) g_bsum[blockIdx.x] = excl + v;   // block total
}

__global__ void scan_bsum_kernel() {     // 1 block x 128
    __shared__ int sh[128];
    const int t = threadIdx.x;
    int v = (t < NB_SCAN) ? g_bsum[t] : 0;
    sh[t] = v;
    __syncthreads();
    for (int o = 1; o < 128; o <<= 1) {
        int u = (t >= o) ? sh[t - o] : 0;
        __syncthreads();
        sh[t] += u;
        __syncthreads();
    }
    if (t < NB_SCAN) g_boff[t] = sh[t] - v;
    if (t == 127)    g_off[N_NODES] = sh[127];
}

// ---- finalize offsets + dinv + cursor -------------------------------------
__global__ void dinv_kernel() {
    int i = blockIdx.x * blockDim.x + threadIdx.x;
    if (i < N_NODES) {
        int off = g_off[i] + g_boff[i >> 10];
        g_off[i]    = off;
        g_cursor[i] = off;
        g_dinv[i]   = rsqrtf((float)g_ecnt[i] + 1.0f);
    }
}

// ---- CSR fill -------------------------------------------------------------
__global__ void fill_kernel(const int* __restrict__ src, const int* __restrict__ dst) {
    int stride = gridDim.x * blockDim.x;
    for (int e = blockIdx.x * blockDim.x + threadIdx.x; e < N_EDGES; e += stride) {
        int s = src[e];
        int d = dst[e];
        int pos = atomicAdd(&g_cursor[d], 1);
        float w = g_dinv[s] * g_dinv[d];
        g_csr[pos] = make_int2(s, __float_as_int(w));
    }
}

// ---- GEMM: xw = in @ W  (fp16 output) -------------------------------------
template<int FIN, int FOUT, int KCHUNK>
__global__ void gemm_kernel(const float* __restrict__ in,
                            const float* __restrict__ W,
                            __half* __restrict__ xw)
{
    constexpr int ROWS = 16;
    __shared__ float Ws[KCHUNK][FOUT];
    __shared__ float hs[ROWS][KCHUNK];

    const int row0 = blockIdx.x * ROWS;
    const int tid  = threadIdx.x;

    float acc[ROWS];
#pragma unroll
    for (int r = 0; r < ROWS; r++) acc[r] = 0.0f;

    for (int kc = 0; kc < FIN; kc += KCHUNK) {
#pragma unroll
        for (int i = tid; i < KCHUNK * FOUT; i += FOUT)
            Ws[i / FOUT][tid] = W[(kc + i / FOUT) * FOUT + tid];
        constexpr int HV = ROWS * KCHUNK / 4;
        for (int i = tid; i < HV; i += FOUT) {
            int r  = i / (KCHUNK / 4);
            int c4 = i % (KCHUNK / 4);
            float4 v = *reinterpret_cast<const float4*>(
                &in[(size_t)(row0 + r) * FIN + kc + c4 * 4]);
            *reinterpret_cast<float4*>(&hs[r][c4 * 4]) = v;
        }
        __syncthreads();

#pragma unroll
        for (int k = 0; k < KCHUNK; k += 4) {
            float w0 = Ws[k + 0][tid];
            float w1 = Ws[k + 1][tid];
            float w2 = Ws[k + 2][tid];
            float w3 = Ws[k + 3][tid];
#pragma unroll
            for (int r = 0; r < ROWS; r++) {
                float4 h4 = *reinterpret_cast<const float4*>(&hs[r][k]);
                float a = acc[r];
                a = fmaf(h4.x, w0, a);
                a = fmaf(h4.y, w1, a);
                a = fmaf(h4.z, w2, a);
                a = fmaf(h4.w, w3, a);
                acc[r] = a;
            }
        }
        __syncthreads();
    }

#pragma unroll
    for (int r = 0; r < ROWS; r++)
        xw[(size_t)(row0 + r) * FOUT + tid] = __float2half_rn(acc[r]);
}

// ---- fused CSR aggregation + self-loop + bias + BN + ReLU (+ pool) --------
// One warp per dst node; fp16 gathers, fp32 accumulate.
template<int FOUT, bool POOL>
__global__ void agg_kernel(const __half* __restrict__ xw,
                           const float* __restrict__ bias,
                           const float* __restrict__ bn_g,
                           const float* __restrict__ bn_b,
                           const float* __restrict__ bn_m,
                           const float* __restrict__ bn_v,
                           float* __restrict__ out,
                           const int* __restrict__ batch)
{
    constexpr int VEC = FOUT / 32;        // 4 (FOUT=128) or 2 (FOUT=64)
    __shared__ float s_sc [FOUT];
    __shared__ float s_shb[FOUT];

    const int tid  = threadIdx.x;
    const int lane = tid & 31;
    const int wid  = tid >> 5;

    if (tid < FOUT) {
        float sc = bn_g[tid] * rsqrtf(bn_v[tid] + BN_EPS);
        s_sc [tid] = sc;
        s_shb[tid] = sc * (bias[tid] - bn_m[tid]) + bn_b[tid];
    }
    __syncthreads();

    const int node = blockIdx.x * 8 + wid;
    if (node >= N_NODES) return;

    const int beg = g_off[node];
    const int end = g_off[node + 1];

    float acc[VEC];
#pragma unroll
    for (int k = 0; k < VEC; k++) acc[k] = 0.0f;

    // lane's slice of a row: VEC halves at [row*FOUT + lane*VEC]
    auto gather = [&](int s, float wgt) {
        if constexpr (VEC == 4) {
            uint2 raw = *reinterpret_cast<const uint2*>(xw + (size_t)s * FOUT + lane * 4);
            float2 f0 = __half22float2(*reinterpret_cast<__half2*>(&raw.x));
            float2 f1 = __half22float2(*reinterpret_cast<__half2*>(&raw.y));
            acc[0] = fmaf(f0.x, wgt, acc[0]);
            acc[1] = fmaf(f0.y, wgt, acc[1]);
            acc[2] = fmaf(f1.x, wgt, acc[2]);
            acc[3] = fmaf(f1.y, wgt, acc[3]);
        } else {
            __half2 raw = *reinterpret_cast<const __half2*>(xw + (size_t)s * FOUT + lane * 2);
            float2 f0 = __half22float2(raw);
            acc[0] = fmaf(f0.x, wgt, acc[0]);
            acc[1] = fmaf(f0.y, wgt, acc[1]);
        }
    };

    int b = beg;
    const int nfull = (end - beg) & ~31;
    for (; b < beg + nfull; b += 32) {
        int2 pk = g_csr[b + lane];
#pragma unroll 8
        for (int j = 0; j < 32; j++) {
            int   s   = __shfl_sync(0xffffffffu, pk.x, j);
            float wgt = __int_as_float(__shfl_sync(0xffffffffu, pk.y, j));
            gather(s, wgt);
        }
    }
    if (b < end) {
        int e = b + lane;
        int   ssrc = 0;
        float swgt = 0.0f;
        if (e < end) {
            int2 pk = g_csr[e];
            ssrc = pk.x;
            swgt = __int_as_float(pk.y);
        }
        int cnt = end - b;
        for (int j = 0; j < cnt; j++) {
            int   s   = __shfl_sync(0xffffffffu, ssrc, j);
            float wgt = __shfl_sync(0xffffffffu, swgt, j);
            gather(s, wgt);
        }
    }

    // self loop
    {
        float di = g_dinv[node];
        gather(node, di * di);
    }

    // BN + ReLU
    float y[VEC];
#pragma unroll
    for (int k = 0; k < VEC; k++) {
        int col = lane * VEC + k;
        y[k] = fmaxf(fmaf(acc[k], s_sc[col], s_shb[col]), 0.0f);
    }

    if constexpr (POOL) {
        int g = batch[node];
#pragma unroll
        for (int k = 0; k < VEC; k++)
            red_add_f32(&g_sums[(size_t)g * 64 + lane * VEC + k], y[k]);
        if (lane == 0) red_add_f32(&g_cnt[g], 1.0f);
    } else {
        if constexpr (VEC == 4) {
            reinterpret_cast<float4*>(out)[(size_t)node * 32 + lane] =
                make_float4(y[0], y[1], y[2], y[3]);
        } else {
            reinterpret_cast<float2*>(out)[(size_t)node * 32 + lane] =
                make_float2(y[0], y[1]);
        }
    }
}

// ---- pooling init ---------------------------------------------------------
__global__ void pool_zero_kernel() {
    int i = blockIdx.x * blockDim.x + threadIdx.x;
    if (i < N_GRAPHS * 64) g_sums[i] = 0.0f;
    if (i < N_GRAPHS)      g_cnt[i]  = 0.0f;
}

// ---- MLP head: one block (128 thr) per graph ------------------------------
__global__ void head_kernel(const float* __restrict__ fw0, const float* __restrict__ fb0,
                            const float* __restrict__ fw1, const float* __restrict__ fb1,
                            const float* __restrict__ ow,  const float* __restrict__ ob,
                            float* __restrict__ out)
{
    __shared__ float pooled[64], h0[128], h1[64];
    const int g = blockIdx.x;
    const int t = threadIdx.x;

    float inv = 1.0f / fmaxf(g_cnt[g], 1.0f);
    if (t < 64) pooled[t] = g_sums[(size_t)g * 64 + t] * inv;
    __syncthreads();

    float a = fb0[t];
#pragma unroll
    for (int k = 0; k < 64; k++) a = fmaf(pooled[k], fw0[k * 128 + t], a);
    h0[t] = fmaxf(a, 0.0f);
    __syncthreads();

    if (t < 64) {
        float b = fb1[t];
#pragma unroll
        for (int k = 0; k < 128; k++) b = fmaf(h0[k], fw1[k * 64 + t], b);
        h1[t] = fmaxf(b, 0.0f);
    }
    __syncthreads();

    if (t < 2) {
        float o = ob[t];
#pragma unroll
        for (int k = 0; k < 64; k++) o = fmaf(h1[k], ow[k * 2 + t], o);
        out[(size_t)g * 2 + t] = o;
    }
}

// ---------------------------------------------------------------------------
extern "C" void kernel_launch(void* const* d_in, const int* in_sizes, int n_in,
                              void* d_out, int out_size)
{
    const float* x          = (const float*)d_in[0];
    const int*   edge_index = (const int*)  d_in[1];
    const int*   batch      = (const int*)  d_in[2];

    int p = 3;
    if (in_sizes[3] == 1) p = 4;   // num_graphs scalar, if materialized

    const float* W [3]; const float* B [3];
    const float* Gm[3]; const float* Be[3];
    const float* Mn[3]; const float* Vr[3];
    for (int l = 0; l < 3; l++) {
        W [l] = (const float*)d_in[p + 6 * l + 0];
        B [l] = (const float*)d_in[p + 6 * l + 1];
        Gm[l] = (const float*)d_in[p + 6 * l + 2];
        Be[l] = (const float*)d_in[p + 6 * l + 3];
        Mn[l] = (const float*)d_in[p + 6 * l + 4];
        Vr[l] = (const float*)d_in[p + 6 * l + 5];
    }
    const float* fw0 = (const float*)d_in[p + 18];
    const float* fb0 = (const float*)d_in[p + 19];
    const float* fw1 = (const float*)d_in[p + 20];
    const float* fb1 = (const float*)d_in[p + 21];
    const float* ow  = (const float*)d_in[p + 22];
    const float* ob  = (const float*)d_in[p + 23];
    float* out = (float*)d_out;

    const int* src = edge_index;
    const int* dst = edge_index + N_EDGES;

    __half* xw;
    float*  bufB;
    cudaGetSymbolAddress((void**)&xw,   g_xw);
    cudaGetSymbolAddress((void**)&bufB, g_bufB);

    // CSR build
    deg_zero_kernel<<<(N_NODES + 255) / 256, 256>>>();
    deg_count_kernel<<<2048, 256>>>(dst);
    scan_blocks_kernel<<<NB_SCAN, 1024>>>();
    scan_bsum_kernel<<<1, 128>>>();
    dinv_kernel<<<(N_NODES + 255) / 256, 256>>>();
    fill_kernel<<<2048, 256>>>(src, dst);

    const int GEMM_BLOCKS = N_NODES / 16;            // 6250 exact
    const int AGG_BLOCKS  = (N_NODES + 7) / 8;       // 12500

    // layer 0: x[36] -> xw -> B(h)
    gemm_kernel<36, 128, 36><<<GEMM_BLOCKS, 128>>>(x, W[0], xw);
    agg_kernel<128, false><<<AGG_BLOCKS, 256>>>(xw, B[0], Gm[0], Be[0], Mn[0], Vr[0], bufB, nullptr);

    // layer 1: B -> xw -> B(h)
    gemm_kernel<128, 128, 64><<<GEMM_BLOCKS, 128>>>(bufB, W[1], xw);
    agg_kernel<128, false><<<AGG_BLOCKS, 256>>>(xw, B[1], Gm[1], Be[1], Mn[1], Vr[1], bufB, nullptr);

    // layer 2: B -> xw -> pooled sums
    gemm_kernel<128, 64, 64><<<GEMM_BLOCKS, 64>>>(bufB, W[2], xw);
    pool_zero_kernel<<<(N_GRAPHS * 64 + 255) / 256, 256>>>();
    agg_kernel<64, true><<<AGG_BLOCKS, 256>>>(xw, B[2], Gm[2], Be[2], Mn[2], Vr[2], nullptr, batch);

    // head
    head_kernel<<<N_GRAPHS, 128>>>(fw0, fb0, fw1, fb1, ow, ob, out);
}

// round 5
// speedup vs baseline: 2.1557x; 1.0282x over previous
#include <cuda_runtime.h>
#include <cuda_fp16.h>
#include <math.h>

// ---------------------------------------------------------------------------
// MolecularGNN: 3x GCNConv(+BN+ReLU) -> global mean pool -> MLP head
// CSR src-only gather (dinv folded into operand rows), agg-first layer 0.
// ---------------------------------------------------------------------------

#define N_NODES  100000
#define N_EDGES  3200000
#define N_GRAPHS 4096
#define BN_EPS   1e-5f
#define NB_SCAN  98          // ceil(100000/1024)

// ---- scratch (device globals; allocation-free rule) -----------------------
__device__ __align__(256) int    g_ecnt  [N_NODES];
__device__ __align__(256) int    g_off   [N_NODES + 1];
__device__ __align__(256) int    g_cursor[N_NODES];
__device__ __align__(256) int    g_bsum  [NB_SCAN];
__device__ __align__(256) int    g_boff  [NB_SCAN];
__device__ __align__(256) float  g_dinv  [N_NODES];
__device__ __align__(256) int    g_csr   [N_EDGES];        // src only
__device__ __align__(256) __half g_xs    [N_NODES * 36];   // x * dinv (fp16)
__device__ __align__(256) float  g_t     [N_NODES * 36];   // aggregated x
__device__ __align__(256) __half g_xw    [N_NODES * 128];  // (h@W)*dinv (fp16)
__device__ __align__(256) float  g_bufB  [N_NODES * 128];  // h (fp32)
__device__ __align__(256) float  g_sums  [N_GRAPHS * 64];
__device__ __align__(256) float  g_cnt   [N_GRAPHS];

__device__ __forceinline__ void red_add_f32(float* p, float v) {
    asm volatile("red.global.add.f32 [%0], %1;" :: "l"(p), "f"(v) : "memory");
}

// ---- degree count ---------------------------------------------------------
__global__ void deg_count_kernel(const int* __restrict__ dst) {
    int stride = gridDim.x * blockDim.x;
    for (int e = blockIdx.x * blockDim.x + threadIdx.x; e < N_EDGES; e += stride)
        atomicAdd(&g_ecnt[dst[e]], 1);
}

// ---- multi-block exclusive scan over g_ecnt -------------------------------
__global__ void scan_blocks_kernel() {   // NB_SCAN blocks x 1024
    __shared__ int wsum[32];
    const int t    = threadIdx.x;
    const int lane = t & 31;
    const int w    = t >> 5;
    const int i    = blockIdx.x * 1024 + t;
    int v = (i < N_NODES) ? g_ecnt[i] : 0;
    int s = v;
#pragma unroll
    for (int o = 1; o < 32; o <<= 1) {
        int u = __shfl_up_sync(0xffffffffu, s, o);
        if (lane >= o) s += u;
    }
    if (lane == 31) wsum[w] = s;
    __syncthreads();
    if (w == 0) {
        int ws = wsum[lane];
        int tt = ws;
#pragma unroll
        for (int o = 1; o < 32; o <<= 1) {
            int u = __shfl_up_sync(0xffffffffu, tt, o);
            if (lane >= o) tt += u;
        }
        wsum[lane] = tt - ws;   // exclusive warp offset
    }
    __syncthreads();
    int excl = s - v + wsum[w];
    if (i < N_NODES) g_off[i] = excl;
    if (t == 1023) g_bsum[blockIdx.x] = excl + v;   // block total
}

__global__ void scan_bsum_kernel() {     // 1 block x 128
    __shared__ int sh[128];
    const int t = threadIdx.x;
    int v = (t < NB_SCAN) ? g_bsum[t] : 0;
    sh[t] = v;
    __syncthreads();
    for (int o = 1; o < 128; o <<= 1) {
        int u = (t >= o) ? sh[t - o] : 0;
        __syncthreads();
        sh[t] += u;
        __syncthreads();
    }
    if (t < NB_SCAN) g_boff[t] = sh[t] - v;
    if (t == 127)    g_off[N_NODES] = sh[127];
}

// ---- finalize offsets + dinv + cursor -------------------------------------
__global__ void dinv_kernel() {
    int i = blockIdx.x * blockDim.x + threadIdx.x;
    if (i < N_NODES) {
        int off = g_off[i] + g_boff[i >> 10];
        g_off[i]    = off;
        g_cursor[i] = off;
        g_dinv[i]   = rsqrtf((float)g_ecnt[i] + 1.0f);
    }
}

// ---- CSR fill (src only) --------------------------------------------------
__global__ void fill_kernel(const int* __restrict__ src, const int* __restrict__ dst) {
    int stride = gridDim.x * blockDim.x;
    for (int e = blockIdx.x * blockDim.x + threadIdx.x; e < N_EDGES; e += stride) {
        int d = dst[e];
        int pos = atomicAdd(&g_cursor[d], 1);
        g_csr[pos] = src[e];
    }
}

// ---- x * dinv -> fp16 -----------------------------------------------------
__global__ void x2h_kernel(const float* __restrict__ x) {
    int i = blockIdx.x * blockDim.x + threadIdx.x;   // over N_NODES*36
    if (i < N_NODES * 36) {
        int n = i / 36;
        g_xs[i] = __float2half_rn(x[i] * g_dinv[n]);
    }
}

// ---- layer-0 aggregation over 36-wide fp16 rows ---------------------------
// t[d] = dinv[d] * (sum_{j in N(d)} xs[j] + xs[d])
__global__ void agg0_kernel() {
    const int tid  = threadIdx.x;
    const int lane = tid & 31;
    const int wid  = tid >> 5;
    const int node = blockIdx.x * 8 + wid;
    if (node >= N_NODES) return;

    const int beg = g_off[node];
    const int end = g_off[node + 1];

    float a0 = 0.0f, a1 = 0.0f;
    const bool act = (lane < 18);

    auto gather = [&](int s) {
        if (act) {
            __half2 v = *reinterpret_cast<const __half2*>(g_xs + (size_t)s * 36 + lane * 2);
            float2 f = __half22float2(v);
            a0 += f.x; a1 += f.y;
        }
    };

    int b = beg;
    const int nfull = (end - beg) & ~31;
    for (; b < beg + nfull; b += 32) {
        int pk = g_csr[b + lane];
#pragma unroll 8
        for (int j = 0; j < 32; j++) {
            int s = __shfl_sync(0xffffffffu, pk, j);
            gather(s);
        }
    }
    if (b < end) {
        int e = b + lane;
        int ssrc = (e < end) ? g_csr[e] : 0;
        int cnt = end - b;
        for (int j = 0; j < cnt; j++) {
            int s = __shfl_sync(0xffffffffu, ssrc, j);
            gather(s);
        }
    }
    gather(node);   // self loop

    if (act) {
        float di = g_dinv[node];
        *reinterpret_cast<float2*>(g_t + (size_t)node * 36 + lane * 2) =
            make_float2(a0 * di, a1 * di);
    }
}

// ---- GEMM with BN+ReLU epilogue (layer 0): h = relu(sc*(t@W) + shb) -------
template<int FIN, int FOUT, int KCHUNK>
__global__ void gemm_bn_kernel(const float* __restrict__ in,
                               const float* __restrict__ W,
                               const float* __restrict__ bias,
                               const float* __restrict__ bn_g,
                               const float* __restrict__ bn_b,
                               const float* __restrict__ bn_m,
                               const float* __restrict__ bn_v,
                               float* __restrict__ out)
{
    constexpr int ROWS = 16;
    __shared__ float Ws[KCHUNK][FOUT];
    __shared__ float hs[ROWS][KCHUNK];

    const int row0 = blockIdx.x * ROWS;
    const int tid  = threadIdx.x;

    float acc[ROWS];
#pragma unroll
    for (int r = 0; r < ROWS; r++) acc[r] = 0.0f;

    for (int kc = 0; kc < FIN; kc += KCHUNK) {
#pragma unroll
        for (int i = tid; i < KCHUNK * FOUT; i += FOUT)
            Ws[i / FOUT][tid] = W[(kc + i / FOUT) * FOUT + tid];
        constexpr int HV = ROWS * KCHUNK / 4;
        for (int i = tid; i < HV; i += FOUT) {
            int r  = i / (KCHUNK / 4);
            int c4 = i % (KCHUNK / 4);
            float4 v = *reinterpret_cast<const float4*>(
                &in[(size_t)(row0 + r) * FIN + kc + c4 * 4]);
            *reinterpret_cast<float4*>(&hs[r][c4 * 4]) = v;
        }
        __syncthreads();

#pragma unroll
        for (int k = 0; k < KCHUNK; k += 4) {
            float w0 = Ws[k + 0][tid];
            float w1 = Ws[k + 1][tid];
            float w2 = Ws[k + 2][tid];
            float w3 = Ws[k + 3][tid];
#pragma unroll
            for (int r = 0; r < ROWS; r++) {
                float4 h4 = *reinterpret_cast<const float4*>(&hs[r][k]);
                float a = acc[r];
                a = fmaf(h4.x, w0, a);
                a = fmaf(h4.y, w1, a);
                a = fmaf(h4.z, w2, a);
                a = fmaf(h4.w, w3, a);
                acc[r] = a;
            }
        }
        __syncthreads();
    }

    float sc  = bn_g[tid] * rsqrtf(bn_v[tid] + BN_EPS);
    float shb = sc * (bias[tid] - bn_m[tid]) + bn_b[tid];
#pragma unroll
    for (int r = 0; r < ROWS; r++)
        out[(size_t)(row0 + r) * FOUT + tid] = fmaxf(fmaf(acc[r], sc, shb), 0.0f);
}

// ---- GEMM with dinv-scale fp16 epilogue (layers 1,2): xws = (h@W)*dinv ----
template<int FIN, int FOUT, int KCHUNK>
__global__ void gemm_h16_kernel(const float* __restrict__ in,
                                const float* __restrict__ W,
                                __half* __restrict__ xw)
{
    constexpr int ROWS = 16;
    __shared__ float Ws[KCHUNK][FOUT];
    __shared__ float hs[ROWS][KCHUNK];

    const int row0 = blockIdx.x * ROWS;
    const int tid  = threadIdx.x;

    float acc[ROWS];
#pragma unroll
    for (int r = 0; r < ROWS; r++) acc[r] = 0.0f;

    for (int kc = 0; kc < FIN; kc += KCHUNK) {
#pragma unroll
        for (int i = tid; i < KCHUNK * FOUT; i += FOUT)
            Ws[i / FOUT][tid] = W[(kc + i / FOUT) * FOUT + tid];
        constexpr int HV = ROWS * KCHUNK / 4;
        for (int i = tid; i < HV; i += FOUT) {
            int r  = i / (KCHUNK / 4);
            int c4 = i % (KCHUNK / 4);
            float4 v = *reinterpret_cast<const float4*>(
                &in[(size_t)(row0 + r) * FIN + kc + c4 * 4]);
            *reinterpret_cast<float4*>(&hs[r][c4 * 4]) = v;
        }
        __syncthreads();

#pragma unroll
        for (int k = 0; k < KCHUNK; k += 4) {
            float w0 = Ws[k + 0][tid];
            float w1 = Ws[k + 1][tid];
            float w2 = Ws[k + 2][tid];
            float w3 = Ws[k + 3][tid];
#pragma unroll
            for (int r = 0; r < ROWS; r++) {
                float4 h4 = *reinterpret_cast<const float4*>(&hs[r][k]);
                float a = acc[r];
                a = fmaf(h4.x, w0, a);
                a = fmaf(h4.y, w1, a);
                a = fmaf(h4.z, w2, a);
                a = fmaf(h4.w, w3, a);
                acc[r] = a;
            }
        }
        __syncthreads();
    }

#pragma unroll
    for (int r = 0; r < ROWS; r++) {
        int row = row0 + r;
        xw[(size_t)row * FOUT + tid] = __float2half_rn(acc[r] * g_dinv[row]);
    }
}

// ---- fused CSR aggregation + dinv scale + BN + ReLU (+ pool) --------------
// One warp per dst node; pure gather+add on fp16 rows.
template<int FOUT, bool POOL>
__global__ void agg_kernel(const __half* __restrict__ xw,
                           const float* __restrict__ bias,
                           const float* __restrict__ bn_g,
                           const float* __restrict__ bn_b,
                           const float* __restrict__ bn_m,
                           const float* __restrict__ bn_v,
                           float* __restrict__ out,
                           const int* __restrict__ batch)
{
    constexpr int VEC = FOUT / 32;        // 4 (FOUT=128) or 2 (FOUT=64)
    __shared__ float s_sc [FOUT];
    __shared__ float s_shb[FOUT];

    const int tid  = threadIdx.x;
    const int lane = tid & 31;
    const int wid  = tid >> 5;

    if (tid < FOUT) {
        float sc = bn_g[tid] * rsqrtf(bn_v[tid] + BN_EPS);
        s_sc [tid] = sc;
        s_shb[tid] = sc * (bias[tid] - bn_m[tid]) + bn_b[tid];
    }
    __syncthreads();

    const int node = blockIdx.x * 8 + wid;
    if (node >= N_NODES) return;

    const int beg = g_off[node];
    const int end = g_off[node + 1];

    float acc[VEC];
#pragma unroll
    for (int k = 0; k < VEC; k++) acc[k] = 0.0f;

    auto gather = [&](int s) {
        if constexpr (VEC == 4) {
            uint2 raw = *reinterpret_cast<const uint2*>(xw + (size_t)s * FOUT + lane * 4);
            float2 f0 = __half22float2(*reinterpret_cast<__half2*>(&raw.x));
            float2 f1 = __half22float2(*reinterpret_cast<__half2*>(&raw.y));
            acc[0] += f0.x; acc[1] += f0.y;
            acc[2] += f1.x; acc[3] += f1.y;
        } else {
            __half2 raw = *reinterpret_cast<const __half2*>(xw + (size_t)s * FOUT + lane * 2);
            float2 f0 = __half22float2(raw);
            acc[0] += f0.x; acc[1] += f0.y;
        }
    };

    int b = beg;
    const int nfull = (end - beg) & ~31;
    for (; b < beg + nfull; b += 32) {
        int pk = g_csr[b + lane];
#pragma unroll 8
        for (int j = 0; j < 32; j++) {
            int s = __shfl_sync(0xffffffffu, pk, j);
            gather(s);
        }
    }
    if (b < end) {
        int e = b + lane;
        int ssrc = (e < end) ? g_csr[e] : 0;
        int cnt = end - b;
        for (int j = 0; j < cnt; j++) {
            int s = __shfl_sync(0xffffffffu, ssrc, j);
            gather(s);
        }
    }
    gather(node);   // self loop

    // dinv scale + BN + ReLU
    const float di = g_dinv[node];
    float y[VEC];
#pragma unroll
    for (int k = 0; k < VEC; k++) {
        int col = lane * VEC + k;
        y[k] = fmaxf(fmaf(acc[k] * di, s_sc[col], s_shb[col]), 0.0f);
    }

    if constexpr (POOL) {
        int g = batch[node];
#pragma unroll
        for (int k = 0; k < VEC; k++)
            red_add_f32(&g_sums[(size_t)g * 64 + lane * VEC + k], y[k]);
        if (lane == 0) red_add_f32(&g_cnt[g], 1.0f);
    } else {
        if constexpr (VEC == 4) {
            reinterpret_cast<float4*>(out)[(size_t)node * 32 + lane] =
                make_float4(y[0], y[1], y[2], y[3]);
        } else {
            reinterpret_cast<float2*>(out)[(size_t)node * 32 + lane] =
                make_float2(y[0], y[1]);
        }
    }
}

// ---- MLP head: one block (128 thr) per graph ------------------------------
__global__ void head_kernel(const float* __restrict__ fw0, const float* __restrict__ fb0,
                            const float* __restrict__ fw1, const float* __restrict__ fb1,
                            const float* __restrict__ ow,  const float* __restrict__ ob,
                            float* __restrict__ out)
{
    __shared__ float pooled[64], h0[128], h1[64];
    const int g = blockIdx.x;
    const int t = threadIdx.x;

    float inv = 1.0f / fmaxf(g_cnt[g], 1.0f);
    if (t < 64) pooled[t] = g_sums[(size_t)g * 64 + t] * inv;
    __syncthreads();

    float a = fb0[t];
#pragma unroll
    for (int k = 0; k < 64; k++) a = fmaf(pooled[k], fw0[k * 128 + t], a);
    h0[t] = fmaxf(a, 0.0f);
    __syncthreads();

    if (t < 64) {
        float b = fb1[t];
#pragma unroll
        for (int k = 0; k < 128; k++) b = fmaf(h0[k], fw1[k * 64 + t], b);
        h1[t] = fmaxf(b, 0.0f);
    }
    __syncthreads();

    if (t < 2) {
        float o = ob[t];
#pragma unroll
        for (int k = 0; k < 64; k++) o = fmaf(h1[k], ow[k * 2 + t], o);
        out[(size_t)g * 2 + t] = o;
    }
}

// ---------------------------------------------------------------------------
extern "C" void kernel_launch(void* const* d_in, const int* in_sizes, int n_in,
                              void* d_out, int out_size)
{
    const float* x          = (const float*)d_in[0];
    const int*   edge_index = (const int*)  d_in[1];
    const int*   batch      = (const int*)  d_in[2];

    int p = 3;
    if (in_sizes[3] == 1) p = 4;   // num_graphs scalar, if materialized

    const float* W [3]; const float* B [3];
    const float* Gm[3]; const float* Be[3];
    const float* Mn[3]; const float* Vr[3];
    for (int l = 0; l < 3; l++) {
        W [l] = (const float*)d_in[p + 6 * l + 0];
        B [l] = (const float*)d_in[p + 6 * l + 1];
        Gm[l] = (const float*)d_in[p + 6 * l + 2];
        Be[l] = (const float*)d_in[p + 6 * l + 3];
        Mn[l] = (const float*)d_in[p + 6 * l + 4];
        Vr[l] = (const float*)d_in[p + 6 * l + 5];
    }
    const float* fw0 = (const float*)d_in[p + 18];
    const float* fb0 = (const float*)d_in[p + 19];
    const float* fw1 = (const float*)d_in[p + 20];
    const float* fb1 = (const float*)d_in[p + 21];
    const float* ow  = (const float*)d_in[p + 22];
    const float* ob  = (const float*)d_in[p + 23];
    float* out = (float*)d_out;

    const int* src = edge_index;
    const int* dst = edge_index + N_EDGES;

    __half* xw;
    float*  bufB;
    float*  tbuf;
    void *ecntp, *sumsp, *cntp;
    cudaGetSymbolAddress((void**)&xw,   g_xw);
    cudaGetSymbolAddress((void**)&bufB, g_bufB);
    cudaGetSymbolAddress((void**)&tbuf, g_t);
    cudaGetSymbolAddress(&ecntp, g_ecnt);
    cudaGetSymbolAddress(&sumsp, g_sums);
    cudaGetSymbolAddress(&cntp,  g_cnt);

    // CSR build
    cudaMemsetAsync(ecntp, 0, N_NODES * sizeof(int));
    deg_count_kernel<<<2048, 256>>>(dst);
    scan_blocks_kernel<<<NB_SCAN, 1024>>>();
    scan_bsum_kernel<<<1, 128>>>();
    dinv_kernel<<<(N_NODES + 255) / 256, 256>>>();
    fill_kernel<<<2048, 256>>>(src, dst);

    const int GEMM_BLOCKS = N_NODES / 16;            // 6250 exact
    const int AGG_BLOCKS  = (N_NODES + 7) / 8;       // 12500

    // layer 0: xs = x*dinv -> t = Â-gather -> h = relu(bn(t@W0 + b))
    x2h_kernel<<<(N_NODES * 36 + 255) / 256, 256>>>(x);
    agg0_kernel<<<AGG_BLOCKS, 256>>>();
    gemm_bn_kernel<36, 128, 36><<<GEMM_BLOCKS, 128>>>(
        tbuf, W[0], B[0], Gm[0], Be[0], Mn[0], Vr[0], bufB);

    // layer 1
    gemm_h16_kernel<128, 128, 64><<<GEMM_BLOCKS, 128>>>(bufB, W[1], xw);
    agg_kernel<128, false><<<AGG_BLOCKS, 256>>>(xw, B[1], Gm[1], Be[1], Mn[1], Vr[1], bufB, nullptr);

    // layer 2 + pool
    gemm_h16_kernel<128, 64, 64><<<GEMM_BLOCKS, 64>>>(bufB, W[2], xw);
    cudaMemsetAsync(sumsp, 0, N_GRAPHS * 64 * sizeof(float));
    cudaMemsetAsync(cntp,  0, N_GRAPHS * sizeof(float));
    agg_kernel<64, true><<<AGG_BLOCKS, 256>>>(xw, B[2], Gm[2], Be[2], Mn[2], Vr[2], nullptr, batch);

    // head
    head_kernel<<<N_GRAPHS, 128>>>(fw0, fb0, fw1, fb1, ow, ob, out);
}